// round 7
// baseline (speedup 1.0000x reference)
#include <cuda_runtime.h>
#include <cuda_fp16.h>
#include <cstdint>

// Problem constants (ClassicMambaBlock: B=2, L=2048, Dm=1024, E=2048, N=16, R=64, K=3)
static constexpr int BSZ  = 2;
static constexpr int LEN  = 2048;
static constexpr int DM   = 1024;
static constexpr int EE   = 2048;
static constexpr int NN   = 16;
static constexpr int RR   = 64;
static constexpr int SEL  = RR + 2 * NN;   // 96
static constexpr int SELP = 128;           // padded for GEMM3 tiling
static constexpr int MTOT = BSZ * LEN;     // 4096
static constexpr int KSPLIT = 4;           // sel-GEMM K split

// ---------------- scratch (no cudaMalloc allowed) ----------------
__device__ float  g_xz[MTOT * 2 * EE];     // [M,4096]: cols [0,E)=xc, [E,2E)=z (fp32)
__device__ float4 g_dug[MTOT * EE];        // per (t,e): {delta, u, silu(z), -}
__device__ float  g_dbc[MTOT * SEL];       // [M,96]: dt_low | B | C (fp32)
__device__ float  g_part[KSPLIT * MTOT * SELP];  // sel-GEMM split-K partials
// fp16 GEMM operands
__device__ __half g_xh[MTOT * DM];
__device__ __half g_winh[2 * EE * DM];
__device__ __half g_wselh[SELP * EE];      // rows 96..127 zero-padded
__device__ __half g_dtwh[EE * RR];
__device__ __half g_wouth[DM * EE];
__device__ __half g_uh[MTOT * EE];         // conv output (GEMM3 A)
__device__ __half g_dtlh[MTOT * RR];       // dt_low (GEMM4 A), lda=64
__device__ __half g_yh[MTOT * EE];         // scan output (GEMM6 A)

// ================= helpers =================
__device__ __forceinline__ uint32_t smem_u32(const void* p) {
    uint32_t a;
    asm("{ .reg .u64 t; cvta.to.shared.u64 t, %1; cvt.u32.u64 %0, t; }" : "=r"(a) : "l"(p));
    return a;
}
__device__ __forceinline__ void cp_async16(uint32_t dst, const void* src) {
    asm volatile("cp.async.cg.shared.global [%0], [%1], 16;" :: "r"(dst), "l"(src));
}
__device__ __forceinline__ void ldm_x4(uint32_t* r, uint32_t addr) {
    asm volatile("ldmatrix.sync.aligned.m8n8.x4.shared.b16 {%0,%1,%2,%3}, [%4];"
                 : "=r"(r[0]), "=r"(r[1]), "=r"(r[2]), "=r"(r[3]) : "r"(addr));
}
__device__ __forceinline__ void mma_f16(float* d, const uint32_t* a, const uint32_t* b) {
    asm volatile(
        "mma.sync.aligned.m16n8k16.row.col.f32.f16.f16.f32 "
        "{%0,%1,%2,%3}, {%4,%5,%6,%7}, {%8,%9}, {%0,%1,%2,%3};"
        : "+f"(d[0]), "+f"(d[1]), "+f"(d[2]), "+f"(d[3])
        : "r"(a[0]), "r"(a[1]), "r"(a[2]), "r"(a[3]), "r"(b[0]), "r"(b[1]));
}

// ---------------- fp32 -> fp16 convert pass (x + all weights) ----------------
static constexpr int C4_X    = MTOT * DM / 4;
static constexpr int C4_WIN  = 2 * EE * DM / 4;
static constexpr int C4_WSEL = SEL * EE / 4;
static constexpr int C4_DTW  = EE * RR / 4;
static constexpr int C4_WOUT = DM * EE / 4;
static constexpr int C4_PAD  = (SELP - SEL) * EE / 4;
static constexpr int C4_TOT  = C4_X + C4_WIN + C4_WSEL + C4_DTW + C4_WOUT + C4_PAD;

__global__ __launch_bounds__(256)
void to_half_kernel(const float4* __restrict__ x,    __half* __restrict__ xh,
                    const float4* __restrict__ win,  __half* __restrict__ winh,
                    const float4* __restrict__ wsel, __half* __restrict__ wselh,
                    const float4* __restrict__ dtw,  __half* __restrict__ dtwh,
                    const float4* __restrict__ wout, __half* __restrict__ wouth)
{
    int i = blockIdx.x * blockDim.x + threadIdx.x;
    if (i >= C4_TOT) return;
    const float4* src; __half* dst; int j = i;
    if (j < C4_X) { src = x; dst = xh; }
    else if ((j -= C4_X) < C4_WIN) { src = win; dst = winh; }
    else if ((j -= C4_WIN) < C4_WSEL) { src = wsel; dst = wselh; }
    else if ((j -= C4_WSEL) < C4_DTW) { src = dtw; dst = dtwh; }
    else if ((j -= C4_DTW) < C4_WOUT) { src = wout; dst = wouth; }
    else {  // zero pad rows 96..127 of wselh
        j -= C4_WOUT;
        reinterpret_cast<uint2*>(wselh + SEL * EE)[j] = make_uint2(0u, 0u);
        return;
    }
    float4 v = src[j];
    __half2 h01 = __floats2half2_rn(v.x, v.y);
    __half2 h23 = __floats2half2_rn(v.z, v.w);
    uint2 pk = make_uint2(*reinterpret_cast<uint32_t*>(&h01), *reinterpret_cast<uint32_t*>(&h23));
    reinterpret_cast<uint2*>(dst)[j] = pk;
}

// ================= fp16 tensor GEMM: C[M,N] = A[M,K] @ B[N,K]^T, fp32 accum =============
// BK = 64 fp16 (128B rows). smem: 16B unit at (c*ROWS + (r ^ c))*16, c = k/8.
// ldmatrix.x4 fragment loads; STAGES-deep cp.async pipeline.
// Split-K via blockIdx.z: A,B advance by z*K elements; C advances by z*zs.
// EPI: 0=none, 1=softplus(x+bias) -> float2 stores, 3=softplus(x+bias) -> scalar
// stores into float4 array .x (C treated as float4 base).
template<int BM, int BN, int WM, int WN, int STAGES, int EPI>
__global__ __launch_bounds__((BM / WM) * (BN / WN) * 32)
void mma_gemm(const __half* __restrict__ A, const __half* __restrict__ Bw,
              float* __restrict__ C, int K, int lda, int ldb, int ldc,
              const float* __restrict__ bias, int zs)
{
    constexpr int WARPS_M = BM / WM;
    constexpr int WARPS_N = BN / WN;
    constexpr int THREADS = WARPS_M * WARPS_N * 32;
    constexpr int MT = WM / 16;
    constexpr int NT = WN / 8;
    constexpr int STAGE_B = (BM + BN) * 128;
    static_assert(NT % 2 == 0, "NT even");

    A  += (size_t)blockIdx.z * K;
    Bw += (size_t)blockIdx.z * K;
    C  += (size_t)blockIdx.z * zs;

    extern __shared__ char smem[];
    const uint32_t smem_b = smem_u32(smem);

    const int tid  = threadIdx.x;
    const int lane = tid & 31, wid = tid >> 5;
    const int wm = wid % WARPS_M, wn = wid / WARPS_M;
    const int qr = lane >> 2, kin = lane & 3;
    const int m0 = blockIdx.y * BM, n0 = blockIdx.x * BN;
    const int lrow = lane & 15, lcof = lane >> 4;

    float acc[MT][NT][4];
#pragma unroll
    for (int i = 0; i < MT; i++)
#pragma unroll
        for (int j = 0; j < NT; j++)
#pragma unroll
            for (int q = 0; q < 4; q++) acc[i][j][q] = 0.f;

    auto load_chunk = [&](int ck, int slot) {
        const int kt = ck * 64;
        const uint32_t ab = smem_b + slot * STAGE_B;
        const uint32_t bb = ab + BM * 128;
#pragma unroll
        for (int it = 0; it < BM * 8 / THREADS; it++) {
            int idx = tid + it * THREADS;
            int r = idx >> 3, c = idx & 7;
            cp_async16(ab + (uint32_t)(c * BM + (r ^ c)) * 16,
                       A + (size_t)(m0 + r) * lda + kt + c * 8);
        }
#pragma unroll
        for (int it = 0; it < BN * 8 / THREADS; it++) {
            int idx = tid + it * THREADS;
            int r = idx >> 3, c = idx & 7;
            cp_async16(bb + (uint32_t)(c * BN + (r ^ c)) * 16,
                       Bw + (size_t)(n0 + r) * ldb + kt + c * 8);
        }
        asm volatile("cp.async.commit_group;" ::: "memory");
    };

    const int nch = K / 64;
#pragma unroll
    for (int s = 0; s < STAGES - 1; s++)
        if (s < nch) load_chunk(s, s);

    for (int i = 0; i < nch; i++) {
        int w = nch - 1 - i;
        if (w > STAGES - 2) w = STAGES - 2;
        if      (w <= 0) asm volatile("cp.async.wait_group 0;" ::: "memory");
        else if (w == 1) asm volatile("cp.async.wait_group 1;" ::: "memory");
        else if (w == 2) asm volatile("cp.async.wait_group 2;" ::: "memory");
        else             asm volatile("cp.async.wait_group 3;" ::: "memory");
        __syncthreads();

        const uint32_t sa = smem_b + (i % STAGES) * STAGE_B;
        const uint32_t sb = sa + BM * 128;
#pragma unroll
        for (int ks = 0; ks < 4; ks++) {
            const int c = 2 * ks + lcof;
            uint32_t af[MT][4], bf[NT][2];
#pragma unroll
            for (int t = 0; t < MT; t++) {
                const int row = wm * WM + t * 16 + lrow;
                ldm_x4(af[t], sa + (uint32_t)(c * BM + (row ^ c)) * 16);
            }
#pragma unroll
            for (int p = 0; p < NT / 2; p++) {
                const int row = wn * WN + p * 16 + lrow;
                uint32_t r4[4];
                ldm_x4(r4, sb + (uint32_t)(c * BN + (row ^ c)) * 16);
                bf[2 * p][0] = r4[0]; bf[2 * p + 1][0] = r4[1];
                bf[2 * p][1] = r4[2]; bf[2 * p + 1][1] = r4[3];
            }
#pragma unroll
            for (int t = 0; t < MT; t++)
#pragma unroll
                for (int j = 0; j < NT; j++)
                    mma_f16(acc[t][j], af[t], bf[j]);
        }
        __syncthreads();

        const int pre = i + STAGES - 1;
        if (pre < nch) load_chunk(pre, pre % STAGES);
    }

    // ---------------- epilogue ----------------
#pragma unroll
    for (int t = 0; t < MT; t++) {
#pragma unroll
        for (int j = 0; j < NT; j++) {
            const int row = m0 + wm * WM + t * 16 + qr;
            const int col = n0 + wn * WN + j * 8 + kin * 2;
            float v0 = acc[t][j][0], v1 = acc[t][j][1];
            float v2 = acc[t][j][2], v3 = acc[t][j][3];
            if (EPI == 1 || EPI == 3) {
                const float b0 = bias[col], b1 = bias[col + 1];
                float x0 = v0 + b0, x1 = v1 + b1, x2 = v2 + b0, x3 = v3 + b1;
                v0 = (x0 > 20.f) ? x0 : log1pf(__expf(x0));
                v1 = (x1 > 20.f) ? x1 : log1pf(__expf(x1));
                v2 = (x2 > 20.f) ? x2 : log1pf(__expf(x2));
                v3 = (x3 > 20.f) ? x3 : log1pf(__expf(x3));
            }
            if (EPI == 3) {   // scalar stores into float4 array .x slots
                C[((size_t)row * ldc + col) * 4]           = v0;
                C[((size_t)row * ldc + col + 1) * 4]       = v1;
                C[((size_t)(row + 8) * ldc + col) * 4]     = v2;
                C[((size_t)(row + 8) * ldc + col + 1) * 4] = v3;
            } else {
                *reinterpret_cast<float2*>(C + (size_t)row * ldc + col)       = make_float2(v0, v1);
                *reinterpret_cast<float2*>(C + (size_t)(row + 8) * ldc + col) = make_float2(v2, v3);
            }
        }
    }
}

// ---------------- sel-GEMM split-K reduce: dbc fp32 + dt_low fp16 ----------------
__global__ __launch_bounds__(256)
void sel_reduce_kernel(const float* __restrict__ part,
                       float* __restrict__ dbc, __half* __restrict__ dtlh)
{
    int idx = blockIdx.x * blockDim.x + threadIdx.x;   // over MTOT*SEL
    if (idx >= MTOT * SEL) return;
    int row = idx / SEL, col = idx % SEL;
    size_t o = (size_t)row * SELP + col;
    float s = part[o] + part[MTOT * SELP + o] + part[2 * MTOT * SELP + o]
            + part[3 * MTOT * SELP + o];
    dbc[idx] = s;
    if (col < RR) dtlh[(size_t)row * RR + col] = __float2half_rn(s);
}

// ---------------- causal depthwise conv1d (K=3) + bias + SiLU; also silu(z) ----------------
__global__ __launch_bounds__(256)
void conv_silu_kernel(const float* __restrict__ xz,
                      const float* __restrict__ cw,
                      const float* __restrict__ cb,
                      float4* __restrict__ dug,
                      __half* __restrict__ uh)
{
    int idx = blockIdx.x * blockDim.x + threadIdx.x;   // over B*L*E = 8.4M
    int e = idx % EE;
    int bt = idx / EE;
    int t = bt % LEN;
    const float* xc = xz + (size_t)(bt - t) * (2 * EE);

    float acc = cb[e];
    float w0 = cw[e * 3 + 0], w1 = cw[e * 3 + 1], w2 = cw[e * 3 + 2];
    if (t >= 2) acc = fmaf(w0, xc[(size_t)(t - 2) * (2 * EE) + e], acc);
    if (t >= 1) acc = fmaf(w1, xc[(size_t)(t - 1) * (2 * EE) + e], acc);
    acc = fmaf(w2, xc[(size_t)t * (2 * EE) + e], acc);
    float s = acc / (1.f + __expf(-acc));              // silu(conv)
    float zv = xc[(size_t)t * (2 * EE) + EE + e];      // z
    float gz = zv / (1.f + __expf(-zv));               // silu(z)
    float* d4 = reinterpret_cast<float*>(dug + idx);
    d4[1] = s;
    d4[2] = gz;
    uh[idx] = __float2half_rn(s);
}

// ---------------- selective scan: float4 fused loads + packed B/C ----------------
__global__ __launch_bounds__(256)
void scan_kernel(const float4* __restrict__ dug,
                 const float* __restrict__ dbc,
                 const float* __restrict__ A_log,
                 const float* __restrict__ D_param,
                 __half* __restrict__ yout)
{
    const int gid  = blockIdx.x * (blockDim.x >> 4) + (threadIdx.x >> 4); // channel b*E+e
    const int lane = threadIdx.x & 31;
    const int n    = threadIdx.x & 15;
    const int b    = gid / EE;
    const int e    = gid % EE;

    const float An = -__expf(A_log[e * NN + n]);
    const float Dp = D_param[e];

    const float4* gptr = dug + (size_t)b * LEN * EE + e;       // {delta,u,gz,-} per t
    const float*  vptr = dbc + (size_t)b * LEN * SEL + RR + lane;  // B|C packed
    __half*       yptr = yout + (size_t)b * LEN * EE + e;

    float h = 0.f;
    float4 g0 = gptr[0];
    float  v0 = vptr[0];
    float4 g1 = gptr[EE];
    float  v1 = vptr[SEL];

    for (int t = 0; t < LEN; t++) {
        float4 g2 = make_float4(0.f, 0.f, 0.f, 0.f);
        float  v2 = 0.f;
        if (t + 2 < LEN) {
            g2 = gptr[(size_t)(t + 2) * EE];
            v2 = vptr[(size_t)(t + 2) * SEL];
        }
        const float Bc = __shfl_sync(0xffffffffu, v0, n);
        const float Cc = __shfl_sync(0xffffffffu, v0, n + 16);
        float dA = __expf(g0.x * An);
        h = fmaf(dA, h, g0.x * g0.y * Bc);
        float p = h * Cc;
        p += __shfl_xor_sync(0xffffffffu, p, 1);
        p += __shfl_xor_sync(0xffffffffu, p, 2);
        p += __shfl_xor_sync(0xffffffffu, p, 4);
        p += __shfl_xor_sync(0xffffffffu, p, 8);
        if (n == 0)
            yptr[(size_t)t * EE] = __float2half_rn((p + g0.y * Dp) * g0.z);
        g0 = g1; v0 = v1;
        g1 = g2; v1 = v2;
    }
}

// ---------------- launch ----------------
extern "C" void kernel_launch(void* const* d_in, const int* in_sizes, int n_in,
                              void* d_out, int out_size)
{
    const float* x       = (const float*)d_in[0];
    const float* W_in    = (const float*)d_in[1];
    const float* conv_w  = (const float*)d_in[2];
    const float* conv_b  = (const float*)d_in[3];
    const float* W_sel   = (const float*)d_in[4];
    const float* dt_w    = (const float*)d_in[5];
    const float* dt_b    = (const float*)d_in[6];
    const float* A_log   = (const float*)d_in[7];
    const float* D_param = (const float*)d_in[8];
    const float* W_out   = (const float*)d_in[9];
    float* out = (float*)d_out;

    float *xz, *dbc, *part;
    float4* dug;
    __half *xh, *winh, *wselh, *dtwh, *wouth, *uh, *dtlh, *yh;
    cudaGetSymbolAddress((void**)&xz,    g_xz);
    cudaGetSymbolAddress((void**)&dug,   g_dug);
    cudaGetSymbolAddress((void**)&dbc,   g_dbc);
    cudaGetSymbolAddress((void**)&part,  g_part);
    cudaGetSymbolAddress((void**)&xh,    g_xh);
    cudaGetSymbolAddress((void**)&winh,  g_winh);
    cudaGetSymbolAddress((void**)&wselh, g_wselh);
    cudaGetSymbolAddress((void**)&dtwh,  g_dtwh);
    cudaGetSymbolAddress((void**)&wouth, g_wouth);
    cudaGetSymbolAddress((void**)&uh,    g_uh);
    cudaGetSymbolAddress((void**)&dtlh,  g_dtlh);
    cudaGetSymbolAddress((void**)&yh,    g_yh);

    // kernel variants
    auto* k_big = mma_gemm<128,  64, 32, 32, 4, 0>;   // 256 thr, 2 CTAs/SM
    auto* k_dlt = mma_gemm<128, 128, 32, 32, 2, 3>;   // 512 thr, K=64 -> 1 chunk
    auto* k_sel = mma_gemm< 32, 128, 32, 16, 4, 0>;   // 256 thr, split-K

    constexpr int SM_BIG = 4 * (128 +  64) * 128;  // 98304
    constexpr int SM_DLT = 2 * (128 + 128) * 128;  // 65536
    constexpr int SM_SEL = 4 * ( 32 + 128) * 128;  // 81920
    cudaFuncSetAttribute((const void*)k_big, cudaFuncAttributeMaxDynamicSharedMemorySize, SM_BIG);
    cudaFuncSetAttribute((const void*)k_dlt, cudaFuncAttributeMaxDynamicSharedMemorySize, SM_DLT);
    cudaFuncSetAttribute((const void*)k_sel, cudaFuncAttributeMaxDynamicSharedMemorySize, SM_SEL);

    // 0) convert x + weights to fp16 (and zero-pad wselh)
    to_half_kernel<<<(C4_TOT + 255) / 256, 256>>>(
        (const float4*)x, xh, (const float4*)W_in, winh,
        (const float4*)W_sel, wselh, (const float4*)dt_w, dtwh,
        (const float4*)W_out, wouth);

    // 1) xz = x @ W_in^T   [4096, 4096], K=1024
    k_big<<<dim3((2 * EE) / 64, MTOT / 128), 256, SM_BIG>>>(
        xh, winh, xz, DM, DM, DM, 2 * EE, nullptr, 0);

    // 2) u = silu(causal_dwconv(xc) + b); also silu(z) -> dug.{y,z}, uh fp16
    conv_silu_kernel<<<(MTOT * EE) / 256, 256>>>(xz, conv_w, conv_b, dug, uh);

    // 3) sel-GEMM split-K: part[z] = u @ W_sel^T over K-slice z
    k_sel<<<dim3(1, MTOT / 32, KSPLIT), 256, SM_SEL>>>(
        uh, wselh, part, EE / KSPLIT, EE, EE, SELP, nullptr, MTOT * SELP);
    sel_reduce_kernel<<<(MTOT * SEL + 255) / 256, 256>>>(part, dbc, dtlh);

    // 4) delta = softplus(dt_low @ dt_w^T + dt_b) -> dug.x   [4096, 2048], K=64
    k_dlt<<<dim3(EE / 128, MTOT / 128), 512, SM_DLT>>>(
        dtlh, dtwh, (float*)dug, RR, RR, RR, EE, dt_b, 0);

    // 5) selective scan + D-skip + z-gating -> y (fp16)
    scan_kernel<<<(BSZ * EE) / 16, 256>>>(dug, dbc, A_log, D_param, yh);

    // 6) out = y @ W_out^T   [4096, 1024], K=2048
    k_big<<<dim3(DM / 64, MTOT / 128), 256, SM_BIG>>>(
        yh, wouth, out, EE, EE, EE, DM, nullptr, 0);
}